// round 8
// baseline (speedup 1.0000x reference)
#include <cuda_runtime.h>
#include <math.h>

#define NN 50000
#define EE 500000
#define TOT (EE + NN)
#define HC 128

// ---------------- device scratch (16B-aligned: float4 access!) ----------------
__device__ __align__(16) float g_feat[NN * HC];
__device__ __align__(16) float g_xl[NN * HC];
__device__ __align__(16) float g_xr[NN * HC];
__device__ int g_rowptr[NN + 1];
__device__ int g_cursor[NN];
__device__ int g_deg[NN];
__device__ int g_col[TOT];
__device__ int g_is64;

// ---------------- edge_index dtype detection ----------------
// If the buffer is really int64, the first 64 values are node ids < NN.
// If it is int32 read as int64, values are pairs a + b*2^32 -> huge.
__global__ void k_detect(const void* __restrict__ ei) {
    if (threadIdx.x != 0 || blockIdx.x != 0) return;
    const long long* p = (const long long*)ei;
    int is64 = 1;
    for (int i = 0; i < 64; i++) {
        long long v = p[i];
        if (v < 0 || v >= (long long)NN) { is64 = 0; break; }
    }
    g_is64 = is64;
}

__device__ __forceinline__ int load_idx(const void* ei, int pos) {
    if (g_is64) return (int)((const long long*)ei)[pos];
    return ((const int*)ei)[pos];
}

// ---------------- CSR build ----------------
__global__ void k_zero_deg(int n) {
    int i = blockIdx.x * blockDim.x + threadIdx.x;
    if (i < n) g_deg[i] = 0;
}

__global__ void k_count(const void* __restrict__ ei, int e, int n) {
    int i = blockIdx.x * blockDim.x + threadIdx.x;
    int tot = e + n;
    if (i >= tot) return;
    int d = (i < e) ? load_idx(ei, e + i) : (i - e);
    if (d < 0 || d >= n) return;   // defensive
    atomicAdd(&g_deg[d], 1);
}

// single-block exclusive scan (n <= 50000): Hillis-Steele per 1024 chunk
__global__ void k_scan(int n) {
    __shared__ int sd[1024];
    __shared__ int soff;
    int tid = threadIdx.x;
    if (tid == 0) soff = 0;
    __syncthreads();
    for (int base = 0; base < n; base += 1024) {
        int i = base + tid;
        int v = (i < n) ? g_deg[i] : 0;
        sd[tid] = v;
        __syncthreads();
        for (int off = 1; off < 1024; off <<= 1) {
            int t = (tid >= off) ? sd[tid - off] : 0;
            __syncthreads();
            sd[tid] += t;
            __syncthreads();
        }
        int excl = soff + sd[tid] - v;
        if (i < n) { g_rowptr[i] = excl; g_cursor[i] = excl; }
        __syncthreads();
        if (tid == 1023) soff += sd[1023];
        __syncthreads();
    }
    if (tid == 0) g_rowptr[n] = soff;
}

__global__ void k_scatter(const void* __restrict__ ei, int e, int n) {
    int i = blockIdx.x * blockDim.x + threadIdx.x;
    int tot = e + n;
    if (i >= tot) return;
    int s, d;
    if (i < e) { s = load_idx(ei, i); d = load_idx(ei, e + i); }
    else       { s = i - e;           d = i - e; }
    if (d < 0 || d >= n || s < 0 || s >= n) return;   // defensive
    int pos = atomicAdd(&g_cursor[d], 1);
    if (pos >= 0 && pos < TOT) g_col[pos] = s;
}

// deterministic ordering: insertion-sort each dst segment by src id
__global__ void k_sortseg(int n) {
    int i = blockIdx.x * blockDim.x + threadIdx.x;
    if (i >= n) return;
    int a = g_rowptr[i], b = g_rowptr[i + 1];
    for (int p = a + 1; p < b; p++) {
        int key = g_col[p];
        int q = p - 1;
        while (q >= a && g_col[q] > key) { g_col[q + 1] = g_col[q]; q--; }
        g_col[q + 1] = key;
    }
}

// ---------------- SGEMM: [n x 128] @ [128 x 128] ----------------
// BM=64, BN=128, BK=32, 256 threads, each thread 8x4 outputs.
// a_is_feat: 0 -> read Aext (harness input), 1 -> read g_feat
// out_which: 0 -> g_xl, 1 -> g_xr
__global__ void k_gemm128(const float* __restrict__ Aext, int a_is_feat,
                          const float* __restrict__ W, int out_which, int n) {
    __shared__ float  As[32][65];       // padded
    __shared__ float4 Ws4[32][32];
    const float* A = a_is_feat ? g_feat : Aext;
    float* out = out_which ? g_xr : g_xl;
    int tid = threadIdx.x;
    int tx = tid & 31, ty = tid >> 5;
    int baser = blockIdx.x * 64;
    float acc[8][4];
#pragma unroll
    for (int i = 0; i < 8; i++)
#pragma unroll
        for (int j = 0; j < 4; j++) acc[i][j] = 0.f;

    const float4* A4 = (const float4*)A;
    const float4* W4 = (const float4*)W;

    for (int kk = 0; kk < 128; kk += 32) {
#pragma unroll
        for (int l = 0; l < 2; l++) {
            int f = tid + l * 256;
            int r = f >> 3, c4 = f & 7;
            float4 v = make_float4(0.f, 0.f, 0.f, 0.f);
            if (baser + r < n) v = A4[(size_t)(baser + r) * 32 + (kk >> 2) + c4];
            As[c4 * 4 + 0][r] = v.x;
            As[c4 * 4 + 1][r] = v.y;
            As[c4 * 4 + 2][r] = v.z;
            As[c4 * 4 + 3][r] = v.w;
        }
#pragma unroll
        for (int l = 0; l < 4; l++) {
            int f = tid + l * 256;
            int r = f >> 5, c4 = f & 31;
            Ws4[r][c4] = W4[(kk + r) * 32 + c4];
        }
        __syncthreads();
#pragma unroll
        for (int k = 0; k < 32; k++) {
            float4 w = Ws4[k][tx];
#pragma unroll
            for (int i = 0; i < 8; i++) {
                float a = As[k][ty * 8 + i];
                acc[i][0] += a * w.x;
                acc[i][1] += a * w.y;
                acc[i][2] += a * w.z;
                acc[i][3] += a * w.w;
            }
        }
        __syncthreads();
    }
    float4* O4 = (float4*)out;
#pragma unroll
    for (int i = 0; i < 8; i++) {
        int row = baser + ty * 8 + i;
        if (row < n)
            O4[(size_t)row * 32 + tx] = make_float4(acc[i][0], acc[i][1], acc[i][2], acc[i][3]);
    }
}

// ---------------- small GEMM: [n x 128] @ [128 x 16] (reads g_feat) ----------------
__global__ void k_gemm16(const float* __restrict__ W, int out_which, int n) {
    __shared__ float Ws[128 * 16];
    float* out = out_which ? g_xr : g_xl;
    int tid = threadIdx.x;
    for (int idx = tid; idx < 128 * 16; idx += 256) Ws[idx] = W[idx];
    __syncthreads();
    int j = tid & 15;
    int row = blockIdx.x * 16 + (tid >> 4);
    if (row >= n) return;
    const float4* a4 = (const float4*)(g_feat + (size_t)row * 128);
    float acc = 0.f;
#pragma unroll
    for (int k4 = 0; k4 < 32; k4++) {
        float4 av = a4[k4];
        acc += av.x * Ws[(k4 * 4 + 0) * 16 + j];
        acc += av.y * Ws[(k4 * 4 + 1) * 16 + j];
        acc += av.z * Ws[(k4 * 4 + 2) * 16 + j];
        acc += av.w * Ws[(k4 * 4 + 3) * 16 + j];
    }
    out[(size_t)row * 16 + j] = acc;
}

// ---------------- GATv2 layer, H=8 C=16 (HC=128), warp per dst node ----------------
// reads g_xl/g_xr, writes g_feat; online softmax; fused bias + BN(eval) + ELU.
__global__ void k_gat128(const float* __restrict__ att, const float* __restrict__ bias,
                         const float* __restrict__ gam, const float* __restrict__ bet,
                         const float* __restrict__ mu, const float* __restrict__ vr,
                         int n) {
    int w = (blockIdx.x * blockDim.x + threadIdx.x) >> 5;
    int lane = threadIdx.x & 31;
    if (w >= n) return;
    int cb = lane * 4;
    float4 xrv = *(const float4*)(g_xr + (size_t)w * HC + cb);
    float4 atv = *(const float4*)(att + cb);
    float m = -INFINITY, den = 0.f;
    float4 acc = make_float4(0.f, 0.f, 0.f, 0.f);
    int p0 = g_rowptr[w], p1 = g_rowptr[w + 1];
    for (int p = p0; p < p1; p++) {
        int s = g_col[p];
        float4 v = *(const float4*)(g_xl + (size_t)s * HC + cb);
        float t0 = v.x + xrv.x, t1 = v.y + xrv.y, t2 = v.z + xrv.z, t3 = v.w + xrv.w;
        t0 = t0 > 0.f ? t0 : 0.2f * t0;
        t1 = t1 > 0.f ? t1 : 0.2f * t1;
        t2 = t2 > 0.f ? t2 : 0.2f * t2;
        t3 = t3 > 0.f ? t3 : 0.2f * t3;
        float part = t0 * atv.x + t1 * atv.y + t2 * atv.z + t3 * atv.w;
        part += __shfl_xor_sync(0xffffffffu, part, 1);
        part += __shfl_xor_sync(0xffffffffu, part, 2);   // 4-lane groups = one head
        float mn = fmaxf(m, part);
        float c  = __expf(m - mn);
        float wg = __expf(part - mn);
        den = den * c + wg;
        acc.x = acc.x * c + wg * v.x;
        acc.y = acc.y * c + wg * v.y;
        acc.z = acc.z * c + wg * v.z;
        acc.w = acc.w * c + wg * v.w;
        m = mn;
    }
    float inv = 1.f / den;
    float o[4];
    o[0] = acc.x * inv; o[1] = acc.y * inv; o[2] = acc.z * inv; o[3] = acc.w * inv;
#pragma unroll
    for (int j = 0; j < 4; j++) {
        int c = cb + j;
        float v = o[j] + bias[c];
        v = (v - mu[c]) * rsqrtf(vr[c] + 1e-5f) * gam[c] + bet[c];
        v = v > 0.f ? v : expm1f(v);
        o[j] = v;
    }
    *(float4*)(g_feat + (size_t)w * HC + cb) = make_float4(o[0], o[1], o[2], o[3]);
}

// ---------------- GATv2 final layer, H=1 C=16, warp per node ----------------
// Fully-converged full-warp design: lanes 16-31 mirror lanes 0-15 (same loads,
// same shuffles, full mask everywhere); only lanes 0-15 store.
__global__ void k_gat16(const float* __restrict__ att, const float* __restrict__ bias,
                        float* __restrict__ out, int n) {
    int node = (blockIdx.x * blockDim.x + threadIdx.x) >> 5;
    int lane = threadIdx.x & 31;
    int ln = lane & 15;
    if (node >= n) return;
    float xrv = g_xr[(size_t)node * 16 + ln];
    float atv = att[ln];
    int p0 = g_rowptr[node], p1 = g_rowptr[node + 1];
    float m = -INFINITY, den = 0.f, accv = 0.f;
    for (int p = p0; p < p1; p++) {
        int s = g_col[p];
        float v = g_xl[(size_t)s * 16 + ln];
        float t = v + xrv;
        t = t > 0.f ? t : 0.2f * t;
        float part = t * atv;
        part += __shfl_xor_sync(0xffffffffu, part, 1);
        part += __shfl_xor_sync(0xffffffffu, part, 2);
        part += __shfl_xor_sync(0xffffffffu, part, 4);
        part += __shfl_xor_sync(0xffffffffu, part, 8);
        float mn = fmaxf(m, part);
        float c  = __expf(m - mn);
        float wg = __expf(part - mn);
        den = den * c + wg;
        accv = accv * c + wg * v;
        m = mn;
    }
    if (lane < 16) out[(size_t)node * 16 + ln] = accv / den + bias[ln];
}

// ---------------- host: kernel launches ONLY ----------------
extern "C" void kernel_launch(void* const* d_in, const int* in_sizes, int n_in,
                              void* d_out, int out_size) {
    const float* x  = (const float*)d_in[0];
    const void*  ei = d_in[1];
    const float* Wl[4] = { (const float*)d_in[2],  (const float*)d_in[6],
                           (const float*)d_in[10], (const float*)d_in[14] };
    const float* Wr[4] = { (const float*)d_in[3],  (const float*)d_in[7],
                           (const float*)d_in[11], (const float*)d_in[15] };
    const float* Aa[4] = { (const float*)d_in[4],  (const float*)d_in[8],
                           (const float*)d_in[12], (const float*)d_in[16] };
    const float* Bb[4] = { (const float*)d_in[5],  (const float*)d_in[9],
                           (const float*)d_in[13], (const float*)d_in[17] };
    const float* Gm[3] = { (const float*)d_in[18], (const float*)d_in[22], (const float*)d_in[26] };
    const float* Bt[3] = { (const float*)d_in[19], (const float*)d_in[23], (const float*)d_in[27] };
    const float* Mu[3] = { (const float*)d_in[20], (const float*)d_in[24], (const float*)d_in[28] };
    const float* Vv[3] = { (const float*)d_in[21], (const float*)d_in[25], (const float*)d_in[29] };

    int n = in_sizes[0] / HC;
    int e = in_sizes[1] / 2;
    int tot = e + n;

    // CSR build (dst is identical for all layers)
    k_detect<<<1, 32>>>(ei);
    k_zero_deg<<<(n + 255) / 256, 256>>>(n);
    k_count<<<(tot + 255) / 256, 256>>>(ei, e, n);
    k_scan<<<1, 1024>>>(n);
    k_scatter<<<(tot + 255) / 256, 256>>>(ei, e, n);
    k_sortseg<<<(n + 255) / 256, 256>>>(n);

    // layers 0-2: 128 -> 8x16 (concat 128) + BN + ELU
    for (int l = 0; l < 3; l++) {
        int a_is_feat = (l > 0) ? 1 : 0;
        k_gemm128<<<(n + 63) / 64, 256>>>(x, a_is_feat, Wl[l], 0, n);
        k_gemm128<<<(n + 63) / 64, 256>>>(x, a_is_feat, Wr[l], 1, n);
        k_gat128<<<(n + 7) / 8, 256>>>(Aa[l], Bb[l], Gm[l], Bt[l], Mu[l], Vv[l], n);
    }
    // final layer: 128 -> 16, H=1 (mean == identity for H=1), bias only
    k_gemm16<<<(n + 15) / 16, 256>>>(Wl[3], 0, n);
    k_gemm16<<<(n + 15) / 16, 256>>>(Wr[3], 1, n);
    k_gat16<<<(n + 7) / 8, 256>>>(Aa[3], Bb[3], (float*)d_out, n);
}

// round 9
// speedup vs baseline: 1.1378x; 1.1378x over previous
#include <cuda_runtime.h>
#include <cuda_bf16.h>
#include <mma.h>
#include <math.h>

using namespace nvcuda;

#define NN 50000
#define NN_PAD 50048          // padded rows so 128-row GEMM tiles never overflow
#define EE 500000
#define TOT (EE + NN)
#define HC 128
#define NB 49                 // ceil(NN/1024)

// ---------------- device scratch (16B-aligned) ----------------
__device__ __align__(16) float g_feat[NN * HC];
__device__ __align__(16) float g_xl[NN_PAD * HC];
__device__ __align__(16) float g_xr[NN_PAD * HC];
__device__ __align__(16) __nv_bfloat16 g_ahi[NN_PAD * HC];
__device__ __align__(16) __nv_bfloat16 g_alo[NN_PAD * HC];
__device__ __align__(16) __nv_bfloat16 g_whi[2 * HC * HC];
__device__ __align__(16) __nv_bfloat16 g_wlo[2 * HC * HC];
__device__ int g_rowptr[NN + 1];
__device__ int g_cursor[NN];
__device__ int g_deg[NN];
__device__ int g_col[TOT];
__device__ int g_bsum[NB];
__device__ int g_boff[NB];
__device__ int g_is64;

// ---------------- edge_index dtype detection ----------------
__global__ void k_detect(const void* __restrict__ ei) {
    if (threadIdx.x != 0 || blockIdx.x != 0) return;
    const long long* p = (const long long*)ei;
    int is64 = 1;
    for (int i = 0; i < 64; i++) {
        long long v = p[i];
        if (v < 0 || v >= (long long)NN) { is64 = 0; break; }
    }
    g_is64 = is64;
}

__device__ __forceinline__ int load_idx(const void* ei, int pos) {
    if (g_is64) return (int)((const long long*)ei)[pos];
    return ((const int*)ei)[pos];
}

// ---------------- CSR build ----------------
__global__ void k_zero_deg(int n) {
    int i = blockIdx.x * blockDim.x + threadIdx.x;
    if (i < n) g_deg[i] = 0;
}

__global__ void k_count(const void* __restrict__ ei, int e, int n) {
    int i = blockIdx.x * blockDim.x + threadIdx.x;
    int tot = e + n;
    if (i >= tot) return;
    int d = (i < e) ? load_idx(ei, e + i) : (i - e);
    if (d < 0 || d >= n) return;
    atomicAdd(&g_deg[d], 1);
}

// parallel scan: (1) per-1024-chunk sums
__global__ void k_bsum(int n) {
    __shared__ int sh[256];
    int b = blockIdx.x;
    int lo = b * 1024, hi = min(n, lo + 1024);
    int s = 0;
    for (int i = lo + threadIdx.x; i < hi; i += 256) s += g_deg[i];
    sh[threadIdx.x] = s;
    __syncthreads();
    for (int off = 128; off > 0; off >>= 1) {
        if (threadIdx.x < off) sh[threadIdx.x] += sh[threadIdx.x + off];
        __syncthreads();
    }
    if (threadIdx.x == 0) g_bsum[b] = sh[0];
}

// (2) tiny serial scan of 49 block sums
__global__ void k_bscan(int n) {
    if (threadIdx.x != 0) return;
    int acc = 0;
    for (int b = 0; b < NB; b++) { g_boff[b] = acc; acc += g_bsum[b]; }
    g_rowptr[n] = acc;
}

// (3) block-local Hillis-Steele + offset
__global__ void k_scan3(int n) {
    __shared__ int sd[1024];
    int b = blockIdx.x;
    int tid = threadIdx.x;
    int i = b * 1024 + tid;
    int v = (i < n) ? g_deg[i] : 0;
    sd[tid] = v;
    __syncthreads();
    for (int off = 1; off < 1024; off <<= 1) {
        int t = (tid >= off) ? sd[tid - off] : 0;
        __syncthreads();
        sd[tid] += t;
        __syncthreads();
    }
    if (i < n) {
        int excl = g_boff[b] + sd[tid] - v;
        g_rowptr[i] = excl;
        g_cursor[i] = excl;
    }
}

__global__ void k_scatter(const void* __restrict__ ei, int e, int n) {
    int i = blockIdx.x * blockDim.x + threadIdx.x;
    int tot = e + n;
    if (i >= tot) return;
    int s, d;
    if (i < e) { s = load_idx(ei, i); d = load_idx(ei, e + i); }
    else       { s = i - e;           d = i - e; }
    if (d < 0 || d >= n || s < 0 || s >= n) return;
    int pos = atomicAdd(&g_cursor[d], 1);
    if (pos >= 0 && pos < TOT) g_col[pos] = s;
}

// deterministic ordering: insertion-sort each dst segment by src id
__global__ void k_sortseg(int n) {
    int i = blockIdx.x * blockDim.x + threadIdx.x;
    if (i >= n) return;
    int a = g_rowptr[i], b = g_rowptr[i + 1];
    for (int p = a + 1; p < b; p++) {
        int key = g_col[p];
        int q = p - 1;
        while (q >= a && g_col[q] > key) { g_col[q + 1] = g_col[q]; q--; }
        g_col[q + 1] = key;
    }
}

// ---------------- bf16 hi/lo split of activations ----------------
// use_feat: 0 -> read xext, 1 -> read g_feat. total4 = n*128/4.
__global__ void k_split(const float* __restrict__ xext, int use_feat, int total4) {
    int i = blockIdx.x * blockDim.x + threadIdx.x;
    if (i >= total4) return;
    const float4* src = (const float4*)(use_feat ? g_feat : xext);
    float4 v = src[i];
    __nv_bfloat16 h0 = __float2bfloat16(v.x);
    __nv_bfloat16 h1 = __float2bfloat16(v.y);
    __nv_bfloat16 h2 = __float2bfloat16(v.z);
    __nv_bfloat16 h3 = __float2bfloat16(v.w);
    __nv_bfloat16 l0 = __float2bfloat16(v.x - __bfloat162float(h0));
    __nv_bfloat16 l1 = __float2bfloat16(v.y - __bfloat162float(h1));
    __nv_bfloat16 l2 = __float2bfloat16(v.z - __bfloat162float(h2));
    __nv_bfloat16 l3 = __float2bfloat16(v.w - __bfloat162float(h3));
    __nv_bfloat162* ph = (__nv_bfloat162*)g_ahi;
    __nv_bfloat162* pl = (__nv_bfloat162*)g_alo;
    ph[i * 2 + 0] = __nv_bfloat162(h0, h1);
    ph[i * 2 + 1] = __nv_bfloat162(h2, h3);
    pl[i * 2 + 0] = __nv_bfloat162(l0, l1);
    pl[i * 2 + 1] = __nv_bfloat162(l2, l3);
}

// split both weight matrices (Wl -> slot 0, Wr -> slot 1), 128x128 each
__global__ void k_splitW(const float* __restrict__ Wlp, const float* __restrict__ Wrp) {
    int i = blockIdx.x * blockDim.x + threadIdx.x;
    if (i >= 2 * HC * HC) return;
    const float* src = (i < HC * HC) ? Wlp : (Wrp - HC * HC);
    float v = src[i];
    __nv_bfloat16 h = __float2bfloat16(v);
    g_whi[i] = h;
    g_wlo[i] = __float2bfloat16(v - __bfloat162float(h));
}

// ---------------- WMMA split-bf16 GEMM: [n x 128] @ [128 x 128] ----------------
// C = Ahi@Whi + Alo@Whi + Ahi@Wlo  (f32 accumulate)
// block: 128x128 output, 256 threads (8 warps, each 32x64).
// grid.y: 0 -> W_l slot, out g_xl; 1 -> W_r slot, out g_xr.
#define ALD 24     // A tile leading dim (elements), 48B rows (16B multiple)
#define BLD 136    // B tile leading dim (elements), 272B rows (16B multiple)
__global__ void k_wgemm(int n) {
    __shared__ __align__(16) __nv_bfloat16 As[128 * ALD];
    __shared__ __align__(16) __nv_bfloat16 Bs[16 * BLD];
    int tid = threadIdx.x;
    int warp = tid >> 5;
    int wm = warp >> 1;          // 0..3 -> row quadrant (32 rows)
    int wn = warp & 1;           // 0..1 -> col half (64 cols)
    int baser = blockIdx.x * 128;
    int wsel = blockIdx.y;

    wmma::fragment<wmma::accumulator, 16, 16, 16, float> acc[2][4];
#pragma unroll
    for (int i = 0; i < 2; i++)
#pragma unroll
        for (int j = 0; j < 4; j++) wmma::fill_fragment(acc[i][j], 0.f);

    const __nv_bfloat16* Wbase_hi = g_whi + wsel * HC * HC;
    const __nv_bfloat16* Wbase_lo = g_wlo + wsel * HC * HC;

    // A-tile load indices: 128 rows x 16 cols, each thread one 16B chunk
    int arow = tid >> 1, ahalf = tid & 1;
    // B-tile load indices: 16 rows x 128 cols
    int brow = tid >> 4, bcol = (tid & 15) * 8;

    for (int seg = 0; seg < 3; seg++) {
        const __nv_bfloat16* Aseg = (seg == 1) ? g_alo : g_ahi;
        const __nv_bfloat16* Wseg = (seg == 2) ? Wbase_lo : Wbase_hi;
        for (int kc = 0; kc < 128; kc += 16) {
            int grow = baser + arow;
            uint4 av = make_uint4(0u, 0u, 0u, 0u);
            if (grow < n) av = *(const uint4*)(Aseg + (size_t)grow * HC + kc + ahalf * 8);
            *(uint4*)(As + arow * ALD + ahalf * 8) = av;
            uint4 bv = *(const uint4*)(Wseg + (size_t)(kc + brow) * HC + bcol);
            *(uint4*)(Bs + brow * BLD + bcol) = bv;
            __syncthreads();

            wmma::fragment<wmma::matrix_a, 16, 16, 16, __nv_bfloat16, wmma::row_major> af[2];
            wmma::fragment<wmma::matrix_b, 16, 16, 16, __nv_bfloat16, wmma::row_major> bf[4];
#pragma unroll
            for (int i = 0; i < 2; i++)
                wmma::load_matrix_sync(af[i], As + (wm * 32 + i * 16) * ALD, ALD);
#pragma unroll
            for (int j = 0; j < 4; j++)
                wmma::load_matrix_sync(bf[j], Bs + wn * 64 + j * 16, BLD);
#pragma unroll
            for (int i = 0; i < 2; i++)
#pragma unroll
                for (int j = 0; j < 4; j++)
                    wmma::mma_sync(acc[i][j], af[i], bf[j], acc[i][j]);
            __syncthreads();
        }
    }

    float* out = wsel ? g_xr : g_xl;
#pragma unroll
    for (int i = 0; i < 2; i++)
#pragma unroll
        for (int j = 0; j < 4; j++) {
            size_t row = baser + wm * 32 + i * 16;     // < NN_PAD by construction
            wmma::store_matrix_sync(out + row * HC + wn * 64 + j * 16,
                                    acc[i][j], HC, wmma::mem_row_major);
        }
}

// ---------------- small GEMM: [n x 128] @ [128 x 16] (reads g_feat, fp32) ----------------
__global__ void k_gemm16(const float* __restrict__ W, int out_which, int n) {
    __shared__ float Ws[128 * 16];
    float* out = out_which ? g_xr : g_xl;
    int tid = threadIdx.x;
    for (int idx = tid; idx < 128 * 16; idx += 256) Ws[idx] = W[idx];
    __syncthreads();
    int j = tid & 15;
    int row = blockIdx.x * 16 + (tid >> 4);
    if (row >= n) return;
    const float4* a4 = (const float4*)(g_feat + (size_t)row * 128);
    float acc = 0.f;
#pragma unroll
    for (int k4 = 0; k4 < 32; k4++) {
        float4 av = a4[k4];
        acc += av.x * Ws[(k4 * 4 + 0) * 16 + j];
        acc += av.y * Ws[(k4 * 4 + 1) * 16 + j];
        acc += av.z * Ws[(k4 * 4 + 2) * 16 + j];
        acc += av.w * Ws[(k4 * 4 + 3) * 16 + j];
    }
    out[(size_t)row * 16 + j] = acc;
}

// ---------------- GATv2 layer, H=8 C=16 (HC=128), warp per dst node ----------------
__global__ void k_gat128(const float* __restrict__ att, const float* __restrict__ bias,
                         const float* __restrict__ gam, const float* __restrict__ bet,
                         const float* __restrict__ mu, const float* __restrict__ vr,
                         int n) {
    int w = (blockIdx.x * blockDim.x + threadIdx.x) >> 5;
    int lane = threadIdx.x & 31;
    if (w >= n) return;
    int cb = lane * 4;
    float4 xrv = *(const float4*)(g_xr + (size_t)w * HC + cb);
    float4 atv = *(const float4*)(att + cb);
    float m = -INFINITY, den = 0.f;
    float4 acc = make_float4(0.f, 0.f, 0.f, 0.f);
    int p0 = g_rowptr[w], p1 = g_rowptr[w + 1];
    for (int p = p0; p < p1; p++) {
        int s = g_col[p];
        float4 v = *(const float4*)(g_xl + (size_t)s * HC + cb);
        float t0 = v.x + xrv.x, t1 = v.y + xrv.y, t2 = v.z + xrv.z, t3 = v.w + xrv.w;
        t0 = t0 > 0.f ? t0 : 0.2f * t0;
        t1 = t1 > 0.f ? t1 : 0.2f * t1;
        t2 = t2 > 0.f ? t2 : 0.2f * t2;
        t3 = t3 > 0.f ? t3 : 0.2f * t3;
        float part = t0 * atv.x + t1 * atv.y + t2 * atv.z + t3 * atv.w;
        part += __shfl_xor_sync(0xffffffffu, part, 1);
        part += __shfl_xor_sync(0xffffffffu, part, 2);   // 4-lane groups = one head
        float mn = fmaxf(m, part);
        float c  = __expf(m - mn);
        float wg = __expf(part - mn);
        den = den * c + wg;
        acc.x = acc.x * c + wg * v.x;
        acc.y = acc.y * c + wg * v.y;
        acc.z = acc.z * c + wg * v.z;
        acc.w = acc.w * c + wg * v.w;
        m = mn;
    }
    float inv = 1.f / den;
    float o[4];
    o[0] = acc.x * inv; o[1] = acc.y * inv; o[2] = acc.z * inv; o[3] = acc.w * inv;
#pragma unroll
    for (int j = 0; j < 4; j++) {
        int c = cb + j;
        float v = o[j] + bias[c];
        v = (v - mu[c]) * rsqrtf(vr[c] + 1e-5f) * gam[c] + bet[c];
        v = v > 0.f ? v : expm1f(v);
        o[j] = v;
    }
    *(float4*)(g_feat + (size_t)w * HC + cb) = make_float4(o[0], o[1], o[2], o[3]);
}

// ---------------- GATv2 final layer, H=1 C=16, warp per node ----------------
__global__ void k_gat16(const float* __restrict__ att, const float* __restrict__ bias,
                        float* __restrict__ out, int n) {
    int node = (blockIdx.x * blockDim.x + threadIdx.x) >> 5;
    int lane = threadIdx.x & 31;
    int ln = lane & 15;
    if (node >= n) return;
    float xrv = g_xr[(size_t)node * 16 + ln];
    float atv = att[ln];
    int p0 = g_rowptr[node], p1 = g_rowptr[node + 1];
    float m = -INFINITY, den = 0.f, accv = 0.f;
    for (int p = p0; p < p1; p++) {
        int s = g_col[p];
        float v = g_xl[(size_t)s * 16 + ln];
        float t = v + xrv;
        t = t > 0.f ? t : 0.2f * t;
        float part = t * atv;
        part += __shfl_xor_sync(0xffffffffu, part, 1);
        part += __shfl_xor_sync(0xffffffffu, part, 2);
        part += __shfl_xor_sync(0xffffffffu, part, 4);
        part += __shfl_xor_sync(0xffffffffu, part, 8);
        float mn = fmaxf(m, part);
        float c  = __expf(m - mn);
        float wg = __expf(part - mn);
        den = den * c + wg;
        accv = accv * c + wg * v;
        m = mn;
    }
    if (lane < 16) out[(size_t)node * 16 + ln] = accv / den + bias[ln];
}

// ---------------- host: kernel launches ONLY ----------------
extern "C" void kernel_launch(void* const* d_in, const int* in_sizes, int n_in,
                              void* d_out, int out_size) {
    const float* x  = (const float*)d_in[0];
    const void*  ei = d_in[1];
    const float* Wl[4] = { (const float*)d_in[2],  (const float*)d_in[6],
                           (const float*)d_in[10], (const float*)d_in[14] };
    const float* Wr[4] = { (const float*)d_in[3],  (const float*)d_in[7],
                           (const float*)d_in[11], (const float*)d_in[15] };
    const float* Aa[4] = { (const float*)d_in[4],  (const float*)d_in[8],
                           (const float*)d_in[12], (const float*)d_in[16] };
    const float* Bb[4] = { (const float*)d_in[5],  (const float*)d_in[9],
                           (const float*)d_in[13], (const float*)d_in[17] };
    const float* Gm[3] = { (const float*)d_in[18], (const float*)d_in[22], (const float*)d_in[26] };
    const float* Bt[3] = { (const float*)d_in[19], (const float*)d_in[23], (const float*)d_in[27] };
    const float* Mu[3] = { (const float*)d_in[20], (const float*)d_in[24], (const float*)d_in[28] };
    const float* Vv[3] = { (const float*)d_in[21], (const float*)d_in[25], (const float*)d_in[29] };

    int n = in_sizes[0] / HC;
    int e = in_sizes[1] / 2;
    int tot = e + n;

    // CSR build (dst identical for all layers)
    k_detect<<<1, 32>>>(ei);
    k_zero_deg<<<(n + 255) / 256, 256>>>(n);
    k_count<<<(tot + 255) / 256, 256>>>(ei, e, n);
    k_bsum<<<NB, 256>>>(n);
    k_bscan<<<1, 32>>>(n);
    k_scan3<<<NB, 1024>>>(n);
    k_scatter<<<(tot + 255) / 256, 256>>>(ei, e, n);
    k_sortseg<<<(n + 255) / 256, 256>>>(n);

    int total4 = n * HC / 4;
    int gx = (n + 127) / 128;

    // layers 0-2: 128 -> 8x16 (concat 128) + BN + ELU, tensor-core projections
    for (int l = 0; l < 3; l++) {
        k_split<<<(total4 + 255) / 256, 256>>>(x, (l > 0) ? 1 : 0, total4);
        k_splitW<<<(2 * HC * HC + 255) / 256, 256>>>(Wl[l], Wr[l]);
        dim3 grid(gx, 2);
        k_wgemm<<<grid, 256>>>(n);
        k_gat128<<<(n + 7) / 8, 256>>>(Aa[l], Bb[l], Gm[l], Bt[l], Mu[l], Vv[l], n);
    }
    // final layer: 128 -> 16, H=1, bias only (fp32, cheap)
    k_gemm16<<<(n + 15) / 16, 256>>>(Wl[3], 0, n);
    k_gemm16<<<(n + 15) / 16, 256>>>(Wr[3], 1, n);
    k_gat16<<<(n + 7) / 8, 256>>>(Aa[3], Bb[3], (float*)d_out, n);
}

// round 10
// speedup vs baseline: 1.2378x; 1.0878x over previous
#include <cuda_runtime.h>
#include <cuda_bf16.h>
#include <mma.h>
#include <math.h>

using namespace nvcuda;

#define NN 50000
#define NN_PAD 50048          // padded rows so 128-row GEMM tiles never overflow
#define EE 500000
#define TOT (EE + NN)
#define HC 128
#define NB 49                 // ceil(NN/1024)
#define LDW 136               // smem leading dim (bf16 elems), 272B rows

// ---------------- device scratch (16B-aligned) ----------------
__device__ __align__(16) float g_feat[NN * HC];
__device__ __align__(16) float g_xl[NN_PAD * HC];
__device__ __align__(16) float g_xr[NN_PAD * HC];
__device__ __align__(16) __nv_bfloat16 g_ahi[NN_PAD * HC];
__device__ __align__(16) __nv_bfloat16 g_alo[NN_PAD * HC];
__device__ __align__(16) __nv_bfloat16 g_whi[2 * HC * HC];
__device__ __align__(16) __nv_bfloat16 g_wlo[2 * HC * HC];
__device__ int g_rowptr[NN + 1];
__device__ int g_cursor[NN];
__device__ int g_deg[NN];
__device__ int g_col[TOT];
__device__ int g_bsum[NB];
__device__ int g_boff[NB];
__device__ int g_is64;

// ---------------- edge_index dtype detection ----------------
__global__ void k_detect(const void* __restrict__ ei) {
    if (threadIdx.x != 0 || blockIdx.x != 0) return;
    const long long* p = (const long long*)ei;
    int is64 = 1;
    for (int i = 0; i < 64; i++) {
        long long v = p[i];
        if (v < 0 || v >= (long long)NN) { is64 = 0; break; }
    }
    g_is64 = is64;
}

__device__ __forceinline__ int load_idx(const void* ei, int pos) {
    if (g_is64) return (int)((const long long*)ei)[pos];
    return ((const int*)ei)[pos];
}

// ---------------- CSR build ----------------
__global__ void k_zero_deg(int n) {
    int i = blockIdx.x * blockDim.x + threadIdx.x;
    if (i < n) g_deg[i] = 0;
}

__global__ void k_count(const void* __restrict__ ei, int e, int n) {
    int i = blockIdx.x * blockDim.x + threadIdx.x;
    int tot = e + n;
    if (i >= tot) return;
    int d = (i < e) ? load_idx(ei, e + i) : (i - e);
    if (d < 0 || d >= n) return;
    atomicAdd(&g_deg[d], 1);
}

__global__ void k_bsum(int n) {
    __shared__ int sh[256];
    int b = blockIdx.x;
    int lo = b * 1024, hi = min(n, lo + 1024);
    int s = 0;
    for (int i = lo + threadIdx.x; i < hi; i += 256) s += g_deg[i];
    sh[threadIdx.x] = s;
    __syncthreads();
    for (int off = 128; off > 0; off >>= 1) {
        if (threadIdx.x < off) sh[threadIdx.x] += sh[threadIdx.x + off];
        __syncthreads();
    }
    if (threadIdx.x == 0) g_bsum[b] = sh[0];
}

__global__ void k_bscan(int n) {
    if (threadIdx.x != 0) return;
    int acc = 0;
    for (int b = 0; b < NB; b++) { g_boff[b] = acc; acc += g_bsum[b]; }
    g_rowptr[n] = acc;
}

__global__ void k_scan3(int n) {
    __shared__ int sd[1024];
    int b = blockIdx.x;
    int tid = threadIdx.x;
    int i = b * 1024 + tid;
    int v = (i < n) ? g_deg[i] : 0;
    sd[tid] = v;
    __syncthreads();
    for (int off = 1; off < 1024; off <<= 1) {
        int t = (tid >= off) ? sd[tid - off] : 0;
        __syncthreads();
        sd[tid] += t;
        __syncthreads();
    }
    if (i < n) {
        int excl = g_boff[b] + sd[tid] - v;
        g_rowptr[i] = excl;
        g_cursor[i] = excl;
    }
}

__global__ void k_scatter(const void* __restrict__ ei, int e, int n) {
    int i = blockIdx.x * blockDim.x + threadIdx.x;
    int tot = e + n;
    if (i >= tot) return;
    int s, d;
    if (i < e) { s = load_idx(ei, i); d = load_idx(ei, e + i); }
    else       { s = i - e;           d = i - e; }
    if (d < 0 || d >= n || s < 0 || s >= n) return;
    int pos = atomicAdd(&g_cursor[d], 1);
    if (pos >= 0 && pos < TOT) g_col[pos] = s;
}

__global__ void k_sortseg(int n) {
    int i = blockIdx.x * blockDim.x + threadIdx.x;
    if (i >= n) return;
    int a = g_rowptr[i], b = g_rowptr[i + 1];
    for (int p = a + 1; p < b; p++) {
        int key = g_col[p];
        int q = p - 1;
        while (q >= a && g_col[q] > key) { g_col[q + 1] = g_col[q]; q--; }
        g_col[q + 1] = key;
    }
}

// ---------------- bf16 hi/lo split of activations ----------------
__global__ void k_split(const float* __restrict__ xext, int use_feat, int total4) {
    int i = blockIdx.x * blockDim.x + threadIdx.x;
    if (i >= total4) return;
    const float4* src = (const float4*)(use_feat ? g_feat : xext);
    float4 v = src[i];
    __nv_bfloat16 h0 = __float2bfloat16(v.x);
    __nv_bfloat16 h1 = __float2bfloat16(v.y);
    __nv_bfloat16 h2 = __float2bfloat16(v.z);
    __nv_bfloat16 h3 = __float2bfloat16(v.w);
    __nv_bfloat16 l0 = __float2bfloat16(v.x - __bfloat162float(h0));
    __nv_bfloat16 l1 = __float2bfloat16(v.y - __bfloat162float(h1));
    __nv_bfloat16 l2 = __float2bfloat16(v.z - __bfloat162float(h2));
    __nv_bfloat16 l3 = __float2bfloat16(v.w - __bfloat162float(h3));
    __nv_bfloat162* ph = (__nv_bfloat162*)g_ahi;
    __nv_bfloat162* pl = (__nv_bfloat162*)g_alo;
    ph[i * 2 + 0] = __nv_bfloat162(h0, h1);
    ph[i * 2 + 1] = __nv_bfloat162(h2, h3);
    pl[i * 2 + 0] = __nv_bfloat162(l0, l1);
    pl[i * 2 + 1] = __nv_bfloat162(l2, l3);
}

__global__ void k_splitW(const float* __restrict__ Wlp, const float* __restrict__ Wrp) {
    int i = blockIdx.x * blockDim.x + threadIdx.x;
    if (i >= 2 * HC * HC) return;
    const float* src = (i < HC * HC) ? Wlp : (Wrp - HC * HC);
    float v = src[i];
    __nv_bfloat16 h = __float2bfloat16(v);
    g_whi[i] = h;
    g_wlo[i] = __float2bfloat16(v - __bfloat162float(h));
}

// ---------------- deep-smem WMMA split-bf16 GEMM: [n x 128] @ [128 x 128] ----------
// C = Ahi@Whi + Alo@Whi + Ahi@Wlo (f32 accum). ONE barrier per block.
// Dynamic smem: Ahi|Alo tiles (128x128) + Whi|Wlo (128x128) all resident.
// grid: (ceil(n/128), 2); grid.y selects Wl->g_xl / Wr->g_xr.
__global__ void k_wgemm(int n) {
    extern __shared__ __align__(16) __nv_bfloat16 sh[];
    __nv_bfloat16* Ah = sh;
    __nv_bfloat16* Al = sh + 128 * LDW;
    __nv_bfloat16* Wh = sh + 2 * 128 * LDW;
    __nv_bfloat16* Wl = sh + 3 * 128 * LDW;
    int tid = threadIdx.x;
    int baser = blockIdx.x * 128;             // +127 < NN_PAD, unguarded
    int wsel = blockIdx.y;
    const __nv_bfloat16* gWh = g_whi + wsel * HC * HC;
    const __nv_bfloat16* gWl = g_wlo + wsel * HC * HC;

#pragma unroll
    for (int it = 0; it < 8; it++) {
        int idx = it * 256 + tid;
        int r = idx >> 4, c = (idx & 15) * 8;
        *(uint4*)(Ah + r * LDW + c) = *(const uint4*)(g_ahi + (size_t)(baser + r) * HC + c);
        *(uint4*)(Al + r * LDW + c) = *(const uint4*)(g_alo + (size_t)(baser + r) * HC + c);
        *(uint4*)(Wh + r * LDW + c) = *(const uint4*)(gWh + r * HC + c);
        *(uint4*)(Wl + r * LDW + c) = *(const uint4*)(gWl + r * HC + c);
    }
    __syncthreads();

    int warp = tid >> 5;
    int wm = warp >> 1;          // 0..3 -> 32-row band
    int wn = warp & 1;           // 0..1 -> 64-col half

    wmma::fragment<wmma::accumulator, 16, 16, 16, float> acc[2][4];
#pragma unroll
    for (int i = 0; i < 2; i++)
#pragma unroll
        for (int j = 0; j < 4; j++) wmma::fill_fragment(acc[i][j], 0.f);

#pragma unroll
    for (int seg = 0; seg < 3; seg++) {
        const __nv_bfloat16* Ap = (seg == 1) ? Al : Ah;
        const __nv_bfloat16* Wp = (seg == 2) ? Wl : Wh;
#pragma unroll
        for (int k = 0; k < 128; k += 16) {
            wmma::fragment<wmma::matrix_a, 16, 16, 16, __nv_bfloat16, wmma::row_major> af[2];
            wmma::fragment<wmma::matrix_b, 16, 16, 16, __nv_bfloat16, wmma::row_major> bf[4];
#pragma unroll
            for (int i = 0; i < 2; i++)
                wmma::load_matrix_sync(af[i], Ap + (wm * 32 + i * 16) * LDW + k, LDW);
#pragma unroll
            for (int j = 0; j < 4; j++)
                wmma::load_matrix_sync(bf[j], Wp + k * LDW + wn * 64 + j * 16, LDW);
#pragma unroll
            for (int i = 0; i < 2; i++)
#pragma unroll
                for (int j = 0; j < 4; j++)
                    wmma::mma_sync(acc[i][j], af[i], bf[j], acc[i][j]);
        }
    }

    float* out = wsel ? g_xr : g_xl;
#pragma unroll
    for (int i = 0; i < 2; i++)
#pragma unroll
        for (int j = 0; j < 4; j++) {
            size_t row = baser + wm * 32 + i * 16;
            wmma::store_matrix_sync(out + row * HC + wn * 64 + j * 16,
                                    acc[i][j], HC, wmma::mem_row_major);
        }
}

// ---------------- small GEMM: [n x 128] @ [128 x 16] (reads g_feat, fp32) -------
__global__ void k_gemm16(const float* __restrict__ W, int out_which, int n) {
    __shared__ float Ws[128 * 16];
    float* out = out_which ? g_xr : g_xl;
    int tid = threadIdx.x;
    for (int idx = tid; idx < 128 * 16; idx += 256) Ws[idx] = W[idx];
    __syncthreads();
    int j = tid & 15;
    int row = blockIdx.x * 16 + (tid >> 4);
    if (row >= n) return;
    const float4* a4 = (const float4*)(g_feat + (size_t)row * 128);
    float acc = 0.f;
#pragma unroll
    for (int k4 = 0; k4 < 32; k4++) {
        float4 av = a4[k4];
        acc += av.x * Ws[(k4 * 4 + 0) * 16 + j];
        acc += av.y * Ws[(k4 * 4 + 1) * 16 + j];
        acc += av.z * Ws[(k4 * 4 + 2) * 16 + j];
        acc += av.w * Ws[(k4 * 4 + 3) * 16 + j];
    }
    out[(size_t)row * 16 + j] = acc;
}

// ---------------- GATv2 layer, H=8 C=16 (HC=128), warp per dst node ------------
__global__ void k_gat128(const float* __restrict__ att, const float* __restrict__ bias,
                         const float* __restrict__ gam, const float* __restrict__ bet,
                         const float* __restrict__ mu, const float* __restrict__ vr,
                         int n) {
    int w = (blockIdx.x * blockDim.x + threadIdx.x) >> 5;
    int lane = threadIdx.x & 31;
    if (w >= n) return;
    int cb = lane * 4;
    float4 xrv = *(const float4*)(g_xr + (size_t)w * HC + cb);
    float4 atv = *(const float4*)(att + cb);
    float m = -INFINITY, den = 0.f;
    float4 acc = make_float4(0.f, 0.f, 0.f, 0.f);
    int p0 = g_rowptr[w], p1 = g_rowptr[w + 1];
    for (int p = p0; p < p1; p++) {
        int s = g_col[p];
        float4 v = *(const float4*)(g_xl + (size_t)s * HC + cb);
        float t0 = v.x + xrv.x, t1 = v.y + xrv.y, t2 = v.z + xrv.z, t3 = v.w + xrv.w;
        t0 = t0 > 0.f ? t0 : 0.2f * t0;
        t1 = t1 > 0.f ? t1 : 0.2f * t1;
        t2 = t2 > 0.f ? t2 : 0.2f * t2;
        t3 = t3 > 0.f ? t3 : 0.2f * t3;
        float part = t0 * atv.x + t1 * atv.y + t2 * atv.z + t3 * atv.w;
        part += __shfl_xor_sync(0xffffffffu, part, 1);
        part += __shfl_xor_sync(0xffffffffu, part, 2);   // 4-lane groups = one head
        float mn = fmaxf(m, part);
        float c  = __expf(m - mn);
        float wg = __expf(part - mn);
        den = den * c + wg;
        acc.x = acc.x * c + wg * v.x;
        acc.y = acc.y * c + wg * v.y;
        acc.z = acc.z * c + wg * v.z;
        acc.w = acc.w * c + wg * v.w;
        m = mn;
    }
    float inv = 1.f / den;
    float o[4];
    o[0] = acc.x * inv; o[1] = acc.y * inv; o[2] = acc.z * inv; o[3] = acc.w * inv;
#pragma unroll
    for (int j = 0; j < 4; j++) {
        int c = cb + j;
        float v = o[j] + bias[c];
        v = (v - mu[c]) * rsqrtf(vr[c] + 1e-5f) * gam[c] + bet[c];
        v = v > 0.f ? v : expm1f(v);
        o[j] = v;
    }
    *(float4*)(g_feat + (size_t)w * HC + cb) = make_float4(o[0], o[1], o[2], o[3]);
}

// ---------------- GATv2 final layer, H=1 C=16, warp per node -------------------
__global__ void k_gat16(const float* __restrict__ att, const float* __restrict__ bias,
                        float* __restrict__ out, int n) {
    int node = (blockIdx.x * blockDim.x + threadIdx.x) >> 5;
    int lane = threadIdx.x & 31;
    int ln = lane & 15;
    if (node >= n) return;
    float xrv = g_xr[(size_t)node * 16 + ln];
    float atv = att[ln];
    int p0 = g_rowptr[node], p1 = g_rowptr[node + 1];
    float m = -INFINITY, den = 0.f, accv = 0.f;
    for (int p = p0; p < p1; p++) {
        int s = g_col[p];
        float v = g_xl[(size_t)s * 16 + ln];
        float t = v + xrv;
        t = t > 0.f ? t : 0.2f * t;
        float part = t * atv;
        part += __shfl_xor_sync(0xffffffffu, part, 1);
        part += __shfl_xor_sync(0xffffffffu, part, 2);
        part += __shfl_xor_sync(0xffffffffu, part, 4);
        part += __shfl_xor_sync(0xffffffffu, part, 8);
        float mn = fmaxf(m, part);
        float c  = __expf(m - mn);
        float wg = __expf(part - mn);
        den = den * c + wg;
        accv = accv * c + wg * v;
        m = mn;
    }
    if (lane < 16) out[(size_t)node * 16 + ln] = accv / den + bias[ln];
}

// ---------------- host: kernel launches ONLY ----------------
extern "C" void kernel_launch(void* const* d_in, const int* in_sizes, int n_in,
                              void* d_out, int out_size) {
    const float* x  = (const float*)d_in[0];
    const void*  ei = d_in[1];
    const float* Wl[4] = { (const float*)d_in[2],  (const float*)d_in[6],
                           (const float*)d_in[10], (const float*)d_in[14] };
    const float* Wr[4] = { (const float*)d_in[3],  (const float*)d_in[7],
                           (const float*)d_in[11], (const float*)d_in[15] };
    const float* Aa[4] = { (const float*)d_in[4],  (const float*)d_in[8],
                           (const float*)d_in[12], (const float*)d_in[16] };
    const float* Bb[4] = { (const float*)d_in[5],  (const float*)d_in[9],
                           (const float*)d_in[13], (const float*)d_in[17] };
    const float* Gm[3] = { (const float*)d_in[18], (const float*)d_in[22], (const float*)d_in[26] };
    const float* Bt[3] = { (const float*)d_in[19], (const float*)d_in[23], (const float*)d_in[27] };
    const float* Mu[3] = { (const float*)d_in[20], (const float*)d_in[24], (const float*)d_in[28] };
    const float* Vv[3] = { (const float*)d_in[21], (const float*)d_in[25], (const float*)d_in[29] };

    int n = in_sizes[0] / HC;
    int e = in_sizes[1] / 2;
    int tot = e + n;
    int total4 = n * HC / 4;
    int gx = (n + 127) / 128;
    int smemBytes = 4 * 128 * LDW * 2;     // 139264

    static int attr_done = 0;
    if (!attr_done) {
        cudaFuncSetAttribute(k_wgemm, cudaFuncAttributeMaxDynamicSharedMemorySize, smemBytes);
        attr_done = 1;
    }

    // layer-0 projection first (no CSR dependency) -> k_wgemm is launch #4 (profiled)
    k_detect<<<1, 32>>>(ei);
    k_split<<<(total4 + 255) / 256, 256>>>(x, 0, total4);
    k_splitW<<<(2 * HC * HC + 255) / 256, 256>>>(Wl[0], Wr[0]);
    {
        dim3 grid(gx, 2);
        k_wgemm<<<grid, 256, smemBytes>>>(n);
    }

    // CSR build (dst identical for all layers)
    k_zero_deg<<<(n + 255) / 256, 256>>>(n);
    k_count<<<(tot + 255) / 256, 256>>>(ei, e, n);
    k_bsum<<<NB, 256>>>(n);
    k_bscan<<<1, 32>>>(n);
    k_scan3<<<NB, 1024>>>(n);
    k_scatter<<<(tot + 255) / 256, 256>>>(ei, e, n);
    k_sortseg<<<(n + 255) / 256, 256>>>(n);

    k_gat128<<<(n + 7) / 8, 256>>>(Aa[0], Bb[0], Gm[0], Bt[0], Mu[0], Vv[0], n);

    for (int l = 1; l < 3; l++) {
        k_split<<<(total4 + 255) / 256, 256>>>(x, 1, total4);
        k_splitW<<<(2 * HC * HC + 255) / 256, 256>>>(Wl[l], Wr[l]);
        dim3 grid(gx, 2);
        k_wgemm<<<grid, 256, smemBytes>>>(n);
        k_gat128<<<(n + 7) / 8, 256>>>(Aa[l], Bb[l], Gm[l], Bt[l], Mu[l], Vv[l], n);
    }
    // final layer: 128 -> 16, H=1, bias only (fp32, cheap)
    k_gemm16<<<(n + 15) / 16, 256>>>(Wl[3], 0, n);
    k_gemm16<<<(n + 15) / 16, 256>>>(Wr[3], 1, n);
    k_gat16<<<(n + 7) / 8, 256>>>(Aa[3], Bb[3], (float*)d_out, n);
}